// round 9
// baseline (speedup 1.0000x reference)
#include <cuda_runtime.h>
#include <math.h>

#define NCTA   128
#define NTHR   512
#define TSTEPS 1024
#define BATCH  64
#define HID    512
#define HB     (HID * BATCH)   // 32768
#define BT     (BATCH * TSTEPS)
#define BH     (BATCH * HID)

typedef unsigned long long u64;

// ---------------- global scratch (allocation-free) --------------------------
__device__ float    g_h0[2][HB];        // transposed: h[k*64 + b]
__device__ float    g_h1[2][HB];
__device__ float    g_yacc[2][BATCH];   // pre-relu y2 accumulators
__device__ unsigned g_flags[NCTA];      // per-CTA arrival generation
__device__ unsigned g_gen;              // broadcast generation

// ---------------- smem layout (float offsets) -------------------------------
// Reduction layout: red[(gate*64 + batch)*20 + slice]  (pad 20 -> 16B-aligned
// float4 rows, conflict-free LDS.128 reduce).
// Region timeline (per step, within one CTA, syncthreads-ordered):
//   R1: redBh(prev) reduced under alpha, then pass-X writes redBi, reduced
//       before beta; gamma window writes redBh(next).  (alias-safe)
//   R2: redA written under beta window, reduced under gamma window.
//   R3: redC written in pass-Y, reduced immediately.
#define OFF_WA    0          // Whh0: 512 x 12 = 6144
#define OFF_WBI   6144       // Wih1            = 6144
#define OFF_WBH   12288      // Whh1            = 6144
#define OFF_WC    18432      // Wo1: 512 x 4    = 2048
#define OFF_BASE  20480      // gi0 ctx part: 12x64 = 768
#define OFF_Y2    21248      // 256
#define OFF_MISC  21504      // wcolA12 bhhA12 biB12 bhB12 bC4 wo2_4 (pad 64)
#define OFF_R1    21568      // 15360  (redBi / redBh)
#define OFF_R2    36928      // 15360  (redA)
#define OFF_R3    52288      // 5120   (redC)
#define SMEM_FLOATS 57408
#define SMEM_BYTES  (SMEM_FLOATS * 4)   // 229,632 B

__device__ __forceinline__ void fma2(u64 &d, u64 a, u64 b) {
    asm("fma.rn.f32x2 %0, %1, %2, %0;" : "+l"(d) : "l"(a), "l"(b));
}
__device__ __forceinline__ u64 dup(float x) {
    u64 r; asm("mov.b64 %0, {%1, %1};" : "=l"(r) : "f"(x)); return r;
}
__device__ __forceinline__ float2 unpack2(u64 v) {
    float2 r; asm("mov.b64 {%0, %1}, %2;" : "=f"(r.x), "=f"(r.y) : "l"(v));
    return r;
}
__device__ __forceinline__ float sigm(float x) { return 1.0f / (1.0f + __expf(-x)); }
__device__ __forceinline__ float tanh_f(float x) {
    return 2.0f / (1.0f + __expf(-2.0f * x)) - 1.0f;
}
__device__ __forceinline__ unsigned ldacq(const unsigned* p) {
    unsigned v;
    asm volatile("ld.acquire.gpu.u32 %0, [%1];" : "=r"(v) : "l"(p) : "memory");
    return v;
}
__device__ __forceinline__ void strel(unsigned* p, unsigned v) {
    asm volatile("st.release.gpu.u32 [%0], %1;" :: "l"(p), "r"(v) : "memory");
}

// Split grid barrier; polling on threads 384..511 overlaps tid<256 work.
__device__ __forceinline__ void bar_arrive(unsigned g) {
    __syncthreads();
    if (threadIdx.x == 0) strel(&g_flags[blockIdx.x], g);
}
__device__ __forceinline__ void bar_wait(unsigned g) {
    if (blockIdx.x == 0) {
        if (threadIdx.x >= 384) {
            while ((int)(ldacq(&g_flags[threadIdx.x - 384]) - g) < 0) { }
        }
        __syncthreads();
        if (threadIdx.x == 0) strel(&g_gen, g);
    } else {
        if (threadIdx.x == 384) {
            while ((int)(ldacq(&g_gen) - g) < 0) { }
        }
        __syncthreads();
    }
}

// 12-gate FMA over 32 retained k-values.
__device__ __forceinline__ void fma12x32(const float* __restrict__ wS, u64* acc,
                                         int kb, const float2* v) {
    #pragma unroll
    for (int i = 0; i < 32; i++) {
        u64 va = dup(v[i].x), vb = dup(v[i].y);
        const ulonglong2* wp = (const ulonglong2*)(wS + (kb + i) * 12);
        ulonglong2 w01 = wp[0], w23 = wp[1], w45 = wp[2];
        fma2(acc[0],  w01.x, va); fma2(acc[1],  w01.x, vb);
        fma2(acc[2],  w01.y, va); fma2(acc[3],  w01.y, vb);
        fma2(acc[4],  w23.x, va); fma2(acc[5],  w23.x, vb);
        fma2(acc[6],  w23.y, va); fma2(acc[7],  w23.y, vb);
        fma2(acc[8],  w45.x, va); fma2(acc[9],  w45.x, vb);
        fma2(acc[10], w45.y, va); fma2(acc[11], w45.y, vb);
    }
}
// Store 12 gate-pair accumulators into padded layout.
__device__ __forceinline__ void store12(float* __restrict__ red, const u64* acc,
                                        int ks, int b0) {
    #pragma unroll
    for (int p = 0; p < 6; p++) {
        float2 f0 = unpack2(acc[2 * p]);        // gates 2p,2p+1 @ batch b0
        float2 f1 = unpack2(acc[2 * p + 1]);    // gates 2p,2p+1 @ batch b0+1
        red[((2 * p)     * 64 + b0)     * 20 + ks] = f0.x;
        red[((2 * p + 1) * 64 + b0)     * 20 + ks] = f0.y;
        red[((2 * p)     * 64 + b0 + 1) * 20 + ks] = f1.x;
        red[((2 * p + 1) * 64 + b0 + 1) * 20 + ks] = f1.y;
    }
}
// Sum 16 slices with 4x LDS.128.
__device__ __forceinline__ float redsum16(const float* __restrict__ red,
                                          int g, int be) {
    const float4* p = (const float4*)(red + (g * 64 + be) * 20);
    float4 a = p[0], b = p[1], c = p[2], d = p[3];
    return (((a.x + a.y) + (a.z + a.w)) + ((b.x + b.y) + (b.z + b.w)))
         + (((c.x + c.y) + (c.z + c.w)) + ((d.x + d.y) + (d.z + d.w)));
}

__global__ void __launch_bounds__(NTHR, 1)
decoder_rnn(const float* __restrict__ ctx,
            const float* __restrict__ Wih0, const float* __restrict__ Whh0,
            const float* __restrict__ bih0, const float* __restrict__ bhh0,
            const float* __restrict__ Wih1, const float* __restrict__ Whh1,
            const float* __restrict__ bih1, const float* __restrict__ bhh1,
            const float* __restrict__ Wo1,  const float* __restrict__ bo1,
            const float* __restrict__ Wo2,  const float* __restrict__ bo2p,
            float* __restrict__ out, int out_size)
{
    extern __shared__ float sm[];
    const int tid = threadIdx.x;
    const int cta = blockIdx.x;
    const int bp  = tid & 31;          // batch pair
    const int b0  = 2 * bp;
    const int ks  = tid >> 5;          // k-slice 0..15 (32 k each)
    const int kb  = ks * 32;
    const int be  = tid & 63;          // elementwise: batch (tid<256)
    const int re  = (tid >> 6) & 3;    // elementwise: local row 0..3
    const int jrow = cta * 4 + re;
    const int gR = re, gZ = 4 + re, gN = 8 + re;

    float* wA   = sm + OFF_WA;
    float* wBi  = sm + OFF_WBI;
    float* wBh  = sm + OFF_WBH;
    float* wC   = sm + OFF_WC;
    float* base = sm + OFF_BASE;
    float* y2   = sm + OFF_Y2;
    float* wcolA = sm + OFF_MISC;      // 12
    float* bhhA  = wcolA + 12;         // 12
    float* biB   = bhhA + 12;          // 12
    float* bhB   = biB + 12;           // 12
    float* bC    = bhB + 12;           // 4
    float* wo2s  = bC + 4;             // 4
    float* redR1 = sm + OFF_R1;        // redBi / redBh (aliased, timeline-safe)
    float* redA  = sm + OFF_R2;
    float* redC  = sm + OFF_R3;

    // ---- prelude: weights -> SMEM, k-major [k][gate] -----------------------
    for (int idx = tid; idx < 12 * 512; idx += NTHR) {
        int g = idx / 512, k = idx & 511;
        int grow = (g >> 2) * 512 + cta * 4 + (g & 3);
        wA [k * 12 + g] = Whh0[grow * 512 + k];
        wBi[k * 12 + g] = Wih1[grow * 512 + k];
        wBh[k * 12 + g] = Whh1[grow * 512 + k];
    }
    for (int idx = tid; idx < 4 * 512; idx += NTHR) {
        int r = idx / 512, k = idx & 511;
        wC[k * 4 + r] = Wo1[(cta * 4 + r) * 512 + k];
    }
    if (tid < 12) {
        int grow = (tid >> 2) * 512 + cta * 4 + (tid & 3);
        wcolA[tid] = Wih0[grow * 513 + 512];   // Wih0 is (1536, 513): prev col
        bhhA[tid]  = bhh0[grow];
        biB[tid]   = bih1[grow];
        bhB[tid]   = bhh1[grow];
    }
    if (tid < 4) {
        bC[tid]   = bo1[cta * 4 + tid];
        wo2s[tid] = Wo2[cta * 4 + tid];
    }
    const float bo2 = bo2p[0];

    // gi0 ctx part (time-invariant): base[g*64+b] = Wih0[grow,:512].ctx[b]+bih0
    {
        int warp = tid >> 5, lane = tid & 31;
        for (int d = warp; d < 12 * 64; d += 16) {
            int g = d >> 6, b = d & 63;
            int grow = (g >> 2) * 512 + cta * 4 + (g & 3);
            const float* wr = Wih0 + (size_t)grow * 513;
            const float* cx = ctx + b * 512;
            float a = 0.0f;
            #pragma unroll 4
            for (int k = lane; k < 512; k += 32) a = fmaf(wr[k], cx[k], a);
            #pragma unroll
            for (int o = 16; o > 0; o >>= 1) a += __shfl_down_sync(0xffffffffu, a, o);
            if (lane == 0) base[g * 64 + b] = a + bih0[grow];
        }
    }

    // zero R1 (t=0: Bh of h1=0 -> bias-only reduce) and initial global state
    for (int idx = tid; idx < 15360; idx += NTHR) redR1[idx] = 0.0f;
    {
        int i = cta * NTHR + tid;
        if (i < HB) { g_h0[0][i] = 0.0f; g_h1[0][i] = 0.0f; }
        if (cta == 0 && tid < BATCH) { g_yacc[0][tid] = 0.0f; g_yacc[1][tid] = 0.0f; }
    }

    unsigned bg = ldacq(&g_gen);   // persistent across graph replays: relative
    bar_arrive(++bg);
    bar_wait(bg);

    // Loop-invariant gi0 sums + carried sums (valid for tid<256).
    float ir0 = 0, iz0 = 0, in0 = 0;
    float c_hr = 0, c_hz = 0, c_hn = 0;       // bhh0 + Whh0.h0(t)
    float wcR = 0, wcZ = 0, wcN = 0;
    if (tid < 256) {
        ir0 = base[gR * 64 + be]; iz0 = base[gZ * 64 + be]; in0 = base[gN * 64 + be];
        c_hr = bhhA[gR]; c_hz = bhhA[gZ]; c_hn = bhhA[gN];
        wcR = wcolA[gR]; wcZ = wcolA[gZ]; wcN = wcolA[gN];
    }
    float c_br = 0, c_bz = 0, c_bn = 0;       // bhh1 + Whh1.h1(t)

    // ---- main recurrence ---------------------------------------------------
    for (int t = 0; t < TSTEPS; t++) {
        const int p = t & 1;

        // ===== phase 1: h0n from carried sums + y(t-1) ======================
        if (tid < 256) {
            float prev_y = 0.0f;
            if (t > 0) prev_y = fmaxf(__ldcg(&g_yacc[(t - 1) & 1][be]) + bo2, 0.0f);
            float r = sigm(ir0 + prev_y * wcR + c_hr);
            float z = sigm(iz0 + prev_y * wcZ + c_hz);
            float n = tanh_f(in0 + prev_y * wcN + r * c_hn);
            float hold = __ldcg(&g_h0[p][jrow * 64 + be]);
            g_h0[1 - p][jrow * 64 + be] = (1.0f - z) * n + z * hold;
            if (cta == 0 && t > 0 && re == 0) out[be * TSTEPS + (t - 1)] = prev_y;
        }
        bar_arrive(++bg);                        // alpha: h0n published

        // Bh(t) reduce under alpha (partials written in prev gamma window)
        if (tid < 256) {
            c_br = bhB[gR] + redsum16(redR1, gR, be);
            c_bz = bhB[gZ] + redsum16(redR1, gZ, be);
            c_bn = bhB[gN] + redsum16(redR1, gN, be);
        }
        bar_wait(bg);                            // alpha
        if (cta == 1 && tid < BATCH) __stcg(&g_yacc[(t + 1) & 1][tid], 0.0f);

        // ===== pass-X: preload h0n once; Bi now, A under beta (reuse regs) ==
        const float* xp = g_h0[1 - p];
        float2 vx[32];
        #pragma unroll
        for (int i = 0; i < 32; i++)
            vx[i] = __ldcg((const float2*)(xp + (kb + i) * 64 + b0));
        {
            u64 acc[12];
            #pragma unroll
            for (int g = 0; g < 12; g++) acc[g] = 0ull;
            fma12x32(wBi, acc, kb, vx);
            store12(redR1, acc, ks, b0);         // redBi
        }
        __syncthreads();
        if (tid < 256) {
            float ir = biB[gR] + redsum16(redR1, gR, be);
            float iz = biB[gZ] + redsum16(redR1, gZ, be);
            float in_ = biB[gN] + redsum16(redR1, gN, be);
            float r = sigm(ir + c_br);
            float z = sigm(iz + c_bz);
            float n = tanh_f(in_ + r * c_bn);
            float hold = __ldcg(&g_h1[p][jrow * 64 + be]);
            g_h1[1 - p][jrow * 64 + be] = (1.0f - z) * n + z * hold;
        }
        bar_arrive(++bg);                        // beta: h1n published

        {   // A(t+1) = Whh0 . h0n, registers reused, under beta
            u64 acc[12];
            #pragma unroll
            for (int g = 0; g < 12; g++) acc[g] = 0ull;
            fma12x32(wA, acc, kb, vx);
            store12(redA, acc, ks, b0);
        }
        bar_wait(bg);                            // beta

        // ===== pass-Y: preload h1n once; C now, Bh under gamma (reuse regs) =
        const float* yp = g_h1[1 - p];
        float2 vy[32];
        #pragma unroll
        for (int i = 0; i < 32; i++)
            vy[i] = __ldcg((const float2*)(yp + (kb + i) * 64 + b0));
        {
            u64 aC[4];
            #pragma unroll
            for (int r = 0; r < 4; r++) aC[r] = 0ull;
            #pragma unroll
            for (int i = 0; i < 32; i++) {
                u64 va = dup(vy[i].x), vb = dup(vy[i].y);
                ulonglong2 wc = *(const ulonglong2*)(wC + (kb + i) * 4);
                fma2(aC[0], wc.x, va); fma2(aC[1], wc.x, vb);
                fma2(aC[2], wc.y, va); fma2(aC[3], wc.y, vb);
            }
            #pragma unroll
            for (int pr = 0; pr < 2; pr++) {
                float2 f0 = unpack2(aC[2 * pr]);
                float2 f1 = unpack2(aC[2 * pr + 1]);
                redC[((2 * pr)     * 64 + b0)     * 20 + ks] = f0.x;
                redC[((2 * pr + 1) * 64 + b0)     * 20 + ks] = f0.y;
                redC[((2 * pr)     * 64 + b0 + 1) * 20 + ks] = f1.x;
                redC[((2 * pr + 1) * 64 + b0 + 1) * 20 + ks] = f1.y;
            }
        }
        __syncthreads();
        if (tid < 256) {
            float s = bC[re] + redsum16(redC, re, be);
            y2[re * 64 + be] = fmaxf(s, 0.0f) * wo2s[re];
        }
        __syncthreads();
        if (tid < 64) {
            float v = y2[tid] + y2[64 + tid] + y2[128 + tid] + y2[192 + tid];
            atomicAdd(&g_yacc[t & 1][tid], v);
        }
        bar_arrive(++bg);                        // gamma: y published

        {   // Bh(t+1) = Whh1 . h1n, registers reused, under gamma
            u64 acc[12];
            #pragma unroll
            for (int g = 0; g < 12; g++) acc[g] = 0ull;
            fma12x32(wBh, acc, kb, vy);
            store12(redR1, acc, ks, b0);         // redBh for next alpha
        }
        __syncthreads();
        if (tid < 256) {   // A(t+1) reduce, still under gamma
            c_hr = bhhA[gR] + redsum16(redA, gR, be);
            c_hz = bhhA[gZ] + redsum16(redA, gZ, be);
            c_hn = bhhA[gN] + redsum16(redA, gN, be);
        }
        bar_wait(bg);                            // gamma
    }

    // ---- epilogue ----------------------------------------------------------
    if (cta == 0 && tid < BATCH)
        out[tid * TSTEPS + (TSTEPS - 1)] = fmaxf(__ldcg(&g_yacc[1][tid]) + bo2, 0.0f);
    if (out_size >= BT + 2 * BH && tid < 256) {
        // final hidden states live in buffer 0 (t=1023: 1-p = 0)
        out[BT + be * HID + jrow]      = __ldcg(&g_h0[0][jrow * 64 + be]);
        out[BT + BH + be * HID + jrow] = __ldcg(&g_h1[0][jrow * 64 + be]);
    }
}

extern "C" void kernel_launch(void* const* d_in, const int* in_sizes, int n_in,
                              void* d_out, int out_size) {
    (void)in_sizes; (void)n_in;
    cudaFuncSetAttribute(decoder_rnn, cudaFuncAttributeMaxDynamicSharedMemorySize,
                         SMEM_BYTES);
    decoder_rnn<<<NCTA, NTHR, SMEM_BYTES>>>(
        (const float*)d_in[0],                           // context_vector
        (const float*)d_in[2],  (const float*)d_in[3],   // W_ih0, W_hh0
        (const float*)d_in[4],  (const float*)d_in[5],   // b_ih0, b_hh0
        (const float*)d_in[6],  (const float*)d_in[7],   // W_ih1, W_hh1
        (const float*)d_in[8],  (const float*)d_in[9],   // b_ih1, b_hh1
        (const float*)d_in[10], (const float*)d_in[11],  // W_o1, b_o1
        (const float*)d_in[12], (const float*)d_in[13],  // W_o2, b_o2
        (float*)d_out, out_size);
}